// round 2
// baseline (speedup 1.0000x reference)
#include <cuda_runtime.h>
#include <math.h>

#define NMAX 32
#define PMAX 128
#define AMAX 25600
#define EPSF 1e-7f

// ---------------- scratch (no allocation allowed) ----------------
__device__ float              g_maxiou[NMAX * AMAX];
__device__ unsigned char      g_idx   [NMAX * AMAX];
__device__ unsigned char      g_forced[NMAX * AMAX];
__device__ unsigned long long g_gtkey [NMAX * PMAX];
__device__ double             g_sums  [3];
__device__ int                g_poscnt[NMAX];

// ---------------- init ----------------
__global__ void init_kernel(int N, int P) {
    int i = blockIdx.x * blockDim.x + threadIdx.x;
    if (i < N * P) g_gtkey[i] = 0ull;
    if (i < 3)     g_sums[i] = 0.0;
    if (i < N)     g_poscnt[i] = 0;
}

// ---------------- assignment: per (image, anchor) ----------------
// anchor-side max/argmax over gts  +  gt-side max/argmax over anchors (packed key)
__global__ void assign_kernel(const float* __restrict__ bbox_true,
                              const float* __restrict__ anchors,
                              int N, int P, int A) {
    int n = blockIdx.y;
    int a = blockIdx.x * blockDim.x + threadIdx.x;

    __shared__ float4 sgt[PMAX];
    __shared__ float  sarea[PMAX];
    __shared__ int    scidx[PMAX];
    __shared__ int    svcnt;
    __shared__ unsigned long long skey[PMAX];

    for (int p = threadIdx.x; p < P; p += blockDim.x) {
        float4 b = ((const float4*)bbox_true)[n * P + p];
        sgt[p] = b;
        sarea[p] = (b.z - b.x) * (b.w - b.y);
        skey[p] = 0ull;
    }
    __syncthreads();
    if (threadIdx.x == 0) {
        int v = 0;
        for (int p = 0; p < P; p++) {
            float4 b = sgt[p];
            if (b.x > 0.f || b.y > 0.f || b.z > 0.f || b.w > 0.f) scidx[v++] = p;
        }
        svcnt = v;
    }
    __syncthreads();
    int v = svcnt;

    bool act = (a < A);
    float ax1 = 0.f, ay1 = 0.f, ax2 = 0.f, ay2 = 0.f, aarea = 0.f;
    if (act) {
        float4 ab = ((const float4*)anchors)[a];
        ax1 = ab.x; ay1 = ab.y; ax2 = ab.z; ay2 = ab.w;
        aarea = (ax2 - ax1) * (ay2 - ay1);
    }

    float best = -1.0f;
    int   bidx = 0;
    if (act) {
        for (int j = 0; j < v; j++) {
            int p = scidx[j];                 // ascending -> first-max tie-break
            float4 b = sgt[p];
            float iw = fmaxf(fminf(ax2, b.z) - fmaxf(ax1, b.x), 0.f);
            float ih = fmaxf(fminf(ay2, b.w) - fmaxf(ay1, b.y), 0.f);
            float inter = iw * ih;
            float iou = inter / (aarea + sarea[p] - inter + EPSF);
            if (iou > best) { best = iou; bidx = p; }
            // gt-side key: higher iou wins; tie -> lowest anchor index wins
            unsigned long long key =
                ((unsigned long long)__float_as_uint(iou) << 32) |
                (unsigned long long)(0xFFFFFFFFu - (unsigned)a);
            if (key > skey[p]) atomicMax(&skey[p], key);
        }
        g_maxiou[n * A + a] = best;
        g_idx   [n * A + a] = (unsigned char)bidx;
        g_forced[n * A + a] = 0;
    }
    __syncthreads();
    for (int p = threadIdx.x; p < P; p += blockDim.x)
        if (skey[p]) atomicMax(&g_gtkey[n * P + p], skey[p]);
}

// ---------------- low-quality-match scatter emulation ----------------
// Reproduces: pos.at[gt_best].max(lowq); true_idx.at[gt_best].set(where(lowq, p, true_idx[gt_best]))
// Duplicate indices -> last update (highest p) wins; updates gathered from ORIGINAL array.
__global__ void scatter_kernel(const float* __restrict__ bbox_true,
                               int N, int P, int A) {
    int n = blockIdx.x;
    int p = threadIdx.x;
    __shared__ int           s_best[PMAX];
    __shared__ unsigned char s_upd [PMAX];
    __shared__ unsigned char s_lowq[PMAX];

    if (p < P) {
        unsigned long long key = g_gtkey[n * P + p];
        int   gbest;
        float gmax;
        if (key == 0ull) { gbest = 0; gmax = -1.0f; }   // invalid/empty column
        else {
            gmax  = __uint_as_float((unsigned)(key >> 32));
            gbest = (int)(0xFFFFFFFFu - (unsigned)(key & 0xFFFFFFFFull));
        }
        const float* b = bbox_true + (size_t)(n * P + p) * 4;
        bool valid = (b[0] > 0.f || b[1] > 0.f || b[2] > 0.f || b[3] > 0.f);
        bool lowq  = valid && (gmax > 0.f);
        s_best[p] = gbest;
        s_lowq[p] = lowq ? 1 : 0;
        s_upd [p] = lowq ? (unsigned char)p : g_idx[n * A + gbest];  // gather from original
    }
    __syncthreads();
    if (p < P) {
        bool winner = true;                    // last-write-wins among duplicates
        for (int q = p + 1; q < P; q++)
            if (s_best[q] == s_best[p]) { winner = false; break; }
        if (winner)    g_idx   [n * A + s_best[p]] = s_upd[p];
        if (s_lowq[p]) g_forced[n * A + s_best[p]] = 1;   // max combiner: idempotent
    }
}

// ---------------- CIoU ----------------
__device__ __forceinline__ float ciou_loss(float4 bt, float4 bp) {
    float ix1 = fmaxf(bt.x, bp.x), iy1 = fmaxf(bt.y, bp.y);
    float ix2 = fminf(bt.z, bp.z), iy2 = fminf(bt.w, bp.w);
    float inter = fmaxf(ix2 - ix1, 0.f) * fmaxf(iy2 - iy1, 0.f);
    float wt = bt.z - bt.x, ht = bt.w - bt.y;
    float wp = bp.z - bp.x, hp = bp.w - bp.y;
    float uni = wt * ht + wp * hp - inter + EPSF;
    float iou = inter / uni;
    float cw = fmaxf(bt.z, bp.z) - fminf(bt.x, bp.x);
    float ch = fmaxf(bt.w, bp.w) - fminf(bt.y, bp.y);
    float c2 = cw * cw + ch * ch + EPSF;
    float dx = bt.x + bt.z - bp.x - bp.z;
    float dy = bt.y + bt.w - bp.y - bp.w;
    float rho2 = (dx * dx + dy * dy) * 0.25f;
    float d = atanf(wt / (ht + EPSF)) - atanf(wp / (hp + EPSF));
    const float k = 4.0f / (float)(M_PI * M_PI);
    float vv = k * d * d;
    float alpha = vv / (1.0f - iou + vv + EPSF);
    return 1.0f - iou + rho2 / c2 + alpha * vv;
}

// ---------------- loss accumulation ----------------
__global__ void loss_kernel(const float* __restrict__ ytrue,
                            const float* __restrict__ bbox_true,
                            const float* __restrict__ conf,
                            const float* __restrict__ logit,
                            const float* __restrict__ bpred,
                            int N, int P, int A, int C) {
    int n = blockIdx.y;
    int a = blockIdx.x * blockDim.x + threadIdx.x;

    float ls = 0.f, lc = 0.f, lb = 0.f;
    int cnt = 0;

    if (a < A) {
        size_t na = (size_t)n * A + a;
        float mi = g_maxiou[na];
        bool pos = (mi >= 0.5f) || (g_forced[na] != 0);
        bool neg = (mi < 0.4f) && !pos;
        float pc = fminf(fmaxf(conf[na], EPSF), 1.0f - EPSF);
        if (pos) {
            ls = -logf(pc);
            cnt = 1;
            int idx = g_idx[na];
            const float* t = ytrue + (size_t)(n * P + idx) * C;
            const float* q = logit + na * C;
            float s = 0.f;
            #pragma unroll 4
            for (int c = 0; c < C; c++) {
                float tv = t[c];
                float qv = fminf(fmaxf(q[c], EPSF), 1.0f - EPSF);
                float pt = tv * qv + (1.0f - tv) * (1.0f - qv);
                float at = tv * 0.25f + (1.0f - tv) * 0.75f;
                float om = 1.0f - pt;
                s -= at * om * om * logf(pt);
            }
            lc = s;
            float4 bt = ((const float4*)bbox_true)[n * P + idx];
            float4 bp = ((const float4*)bpred)[na];
            lb = ciou_loss(bt, bp);
        } else if (neg) {
            ls = -logf(1.0f - pc);
        }
    }

    // block reduction: 3 floats + 1 int
    #pragma unroll
    for (int off = 16; off; off >>= 1) {
        ls  += __shfl_down_sync(0xffffffffu, ls,  off);
        lc  += __shfl_down_sync(0xffffffffu, lc,  off);
        lb  += __shfl_down_sync(0xffffffffu, lb,  off);
        cnt += __shfl_down_sync(0xffffffffu, cnt, off);
    }
    __shared__ float sredS[8], sredC[8], sredB[8];
    __shared__ int   sredN[8];
    int wid = threadIdx.x >> 5, lid = threadIdx.x & 31;
    if (lid == 0) { sredS[wid] = ls; sredC[wid] = lc; sredB[wid] = lb; sredN[wid] = cnt; }
    __syncthreads();
    if (wid == 0) {
        int nw = blockDim.x >> 5;
        ls  = (lid < nw) ? sredS[lid] : 0.f;
        lc  = (lid < nw) ? sredC[lid] : 0.f;
        lb  = (lid < nw) ? sredB[lid] : 0.f;
        cnt = (lid < nw) ? sredN[lid] : 0;
        #pragma unroll
        for (int off = 4; off; off >>= 1) {
            ls  += __shfl_down_sync(0xffffffffu, ls,  off);
            lc  += __shfl_down_sync(0xffffffffu, lc,  off);
            lb  += __shfl_down_sync(0xffffffffu, lb,  off);
            cnt += __shfl_down_sync(0xffffffffu, cnt, off);
        }
        if (lid == 0) {
            if (ls != 0.f) atomicAdd(&g_sums[0], (double)ls);
            if (lc != 0.f) atomicAdd(&g_sums[1], (double)lc);
            if (lb != 0.f) atomicAdd(&g_sums[2], (double)lb);
            if (cnt)       atomicAdd(&g_poscnt[n], cnt);
        }
    }
}

// ---------------- finalize ----------------
__global__ void finalize_kernel(float* __restrict__ out, int N) {
    if (threadIdx.x != 0 || blockIdx.x != 0) return;
    double af = 0.0;
    for (int i = 0; i < N; i++) {
        int c = g_poscnt[i];
        af += (c > 0) ? (double)c : 1.0;
    }
    #pragma unroll
    for (int i = 0; i < 3; i++) {
        double r = g_sums[i] / af;
        if (isnan(r) || isinf(r)) r = 0.0;
        out[i] = (float)r;
    }
}

// ---------------- launch ----------------
extern "C" void kernel_launch(void* const* d_in, const int* in_sizes, int n_in,
                              void* d_out, int out_size) {
    const float* y_true    = (const float*)d_in[0];
    const float* bbox_true = (const float*)d_in[1];
    const float* conf_pred = (const float*)d_in[2];
    const float* logit_pred= (const float*)d_in[3];
    const float* bbox_pred = (const float*)d_in[4];
    const float* anchors   = (const float*)d_in[5];

    int A = in_sizes[5] / 4;
    int N = in_sizes[2] / A;
    int P = in_sizes[1] / (4 * N);
    int C = in_sizes[3] / (N * A);

    init_kernel<<<(N * P + 255) / 256, 256>>>(N, P);

    dim3 gA((A + 255) / 256, N);
    assign_kernel<<<gA, 256>>>(bbox_true, anchors, N, P, A);

    scatter_kernel<<<N, PMAX>>>(bbox_true, N, P, A);

    dim3 gL((A + 255) / 256, N);
    loss_kernel<<<gL, 256>>>(y_true, bbox_true, conf_pred, logit_pred, bbox_pred,
                             N, P, A, C);

    finalize_kernel<<<1, 32>>>((float*)d_out, N);
}